// round 10
// baseline (speedup 1.0000x reference)
#include <cuda_runtime.h>
#include <cuda_bf16.h>
#include <math.h>
#include <stdint.h>

#define BN 65536
#define DD 1024
#define EE 16
#define HH1 128
#define HH2 64
#define RR1 64
#define RR2 32
#define EPSV 1e-5f

// expert tiling: 256 rows x 128 cols (one expert) per CTA, 512 threads
#define TMX 256
#define NCH1 32          // K chunks of 32

// dynamic smem map for expert kernel
#define OXB 0            // 3 stages x 20480 (256 x 40 halves)
#define OWB 61440        // 3 stages x 8704  (32 x 136 halves)
#define OW2 87552        // 128 x 72 halves = 18432
#define OCB 105984       // consts (1024 B) + red (2048 B)
#define SMEM_TOT 109568

// ---------------- device scratch ----------------
__device__ __nv_bfloat16 g_xb[(size_t)BN * DD];
__device__ __nv_bfloat16 g_rW1b[DD * RR1];
__device__ float         g_rb1eff[RR1];
__device__ __nv_bfloat16 g_eW1b[(size_t)EE * DD * HH1];   // [e][d][h] folded
__device__ float         g_eb1eff[EE * HH1];
__device__ __nv_bfloat16 g_eW2b[EE * HH1 * HH2];          // [e][h][j]

// ---------------- helpers ----------------
__device__ __forceinline__ unsigned cvta_s(const void* p) {
    return (unsigned)__cvta_generic_to_shared(p);
}
__device__ __forceinline__ void cp16(void* s, const void* g) {
    asm volatile("cp.async.cg.shared.global [%0], [%1], 16;\n"
                 :: "r"(cvta_s(s)), "l"(g));
}
__device__ __forceinline__ void cp_commit() {
    asm volatile("cp.async.commit_group;\n");
}
template<int N> __device__ __forceinline__ void cp_wait() {
    asm volatile("cp.async.wait_group %0;\n" :: "n"(N));
}
__device__ __forceinline__ void ldm_x4(unsigned r[4], unsigned addr) {
    asm volatile("ldmatrix.sync.aligned.m8n8.x4.shared.b16 {%0,%1,%2,%3}, [%4];"
                 : "=r"(r[0]), "=r"(r[1]), "=r"(r[2]), "=r"(r[3]) : "r"(addr));
}
__device__ __forceinline__ void ldm_x4t(unsigned r[4], unsigned addr) {
    asm volatile("ldmatrix.sync.aligned.m8n8.x4.trans.shared.b16 {%0,%1,%2,%3}, [%4];"
                 : "=r"(r[0]), "=r"(r[1]), "=r"(r[2]), "=r"(r[3]) : "r"(addr));
}
__device__ __forceinline__ void mma16816(float d[4], const unsigned a[4],
                                         unsigned b0, unsigned b1) {
    asm volatile(
        "mma.sync.aligned.m16n8k16.row.col.f32.bf16.bf16.f32 "
        "{%0,%1,%2,%3}, {%4,%5,%6,%7}, {%8,%9}, {%0,%1,%2,%3};"
        : "+f"(d[0]), "+f"(d[1]), "+f"(d[2]), "+f"(d[3])
        : "r"(a[0]), "r"(a[1]), "r"(a[2]), "r"(a[3]), "r"(b0), "r"(b1));
}
__device__ __forceinline__ unsigned packbf(float a, float b) {
    __nv_bfloat162 t = __floats2bfloat162_rn(a, b);
    return *reinterpret_cast<unsigned*>(&t);
}

// ---------------- prep kernels ----------------
__global__ void k_conv_x(const float* __restrict__ x) {
    size_t i = ((size_t)blockIdx.x * 256 + threadIdx.x) * 8;
    float4 v0 = *(const float4*)(x + i);
    float4 v1 = *(const float4*)(x + i + 4);
    uint4 u;
    u.x = packbf(v0.x, v0.y); u.y = packbf(v0.z, v0.w);
    u.z = packbf(v1.x, v1.y); u.w = packbf(v1.z, v1.w);
    *(uint4*)(g_xb + i) = u;
}

__global__ void k_prep_router(const float* __restrict__ rW1, const float* __restrict__ g,
                              const float* __restrict__ be, const float* __restrict__ mn,
                              const float* __restrict__ v, const float* __restrict__ rb1) {
    int b = blockIdx.x, t = threadIdx.x;
    if (b < 256) {
        int i = b * 256 + t;
        int d = i >> 6;
        float rs = g[d] * rsqrtf(v[d] + EPSV);
        g_rW1b[i] = __float2bfloat16(rW1[i] * rs);
    } else {
        int h = b - 256;
        float s = 0.f;
        for (int d = t; d < DD; d += 256) {
            float rs = g[d] * rsqrtf(v[d] + EPSV);
            float sh = be[d] - mn[d] * rs;
            s += sh * rW1[d * RR1 + h];
        }
        __shared__ float red[256];
        red[t] = s; __syncthreads();
        for (int o = 128; o; o >>= 1) { if (t < o) red[t] += red[t + o]; __syncthreads(); }
        if (!t) g_rb1eff[h] = rb1[h] + red[0];
    }
}

// [0,8192): fold eW1 -> bf16; [8192,8704): conv eW2; [8704,10752): fold bias
__global__ void k_prep_expert(const float* __restrict__ eW1, const float* __restrict__ g,
                              const float* __restrict__ v, const float* __restrict__ eW2,
                              const float* __restrict__ be, const float* __restrict__ mn,
                              const float* __restrict__ eb1) {
    int b = blockIdx.x, t = threadIdx.x;
    if (b < 8192) {
        int i = b * 256 + t;
        int ed = i >> 7;
        float sc = g[ed] * rsqrtf(v[ed] + EPSV);
        g_eW1b[i] = __float2bfloat16(eW1[i] * sc);
    } else if (b < 8704) {
        int i = (b - 8192) * 256 + t;
        g_eW2b[i] = __float2bfloat16(eW2[i]);
    } else {
        int bb = b - 8704;
        int e = bb >> 7, h = bb & 127;
        float s = 0.f;
        for (int d = t; d < DD; d += 256) {
            int ed = e * DD + d;
            float sc = g[ed] * rsqrtf(v[ed] + EPSV);
            float sh = be[ed] - mn[ed] * sc;
            s += sh * eW1[(size_t)ed * HH1 + h];
        }
        __shared__ float red[256];
        red[t] = s; __syncthreads();
        for (int o = 128; o; o >>= 1) { if (t < o) red[t] += red[t + o]; __syncthreads(); }
        if (!t) g_eb1eff[bb] = eb1[bb] + red[0];
    }
}

// ---------------- expert kernel: 256 rows x 1 expert, 512 thr, 3-stage cp.async ----------------
__global__ void __launch_bounds__(512, 1)
expert_kernel(const float* __restrict__ eb2, const float* __restrict__ eW3,
              const float* __restrict__ eb3, float* __restrict__ out) {
    extern __shared__ __align__(16) char sm[];
    __nv_bfloat16* H1s = (__nv_bfloat16*)sm;              // [256][136], overlaps stages
    __nv_bfloat16* W2s = (__nv_bfloat16*)(sm + OW2);      // [128][72]
    float* b1s = (float*)(sm + OCB);                      // 128 floats
    float* b2s = (float*)(sm + OCB + 512);                // 64 floats
    float* w3s = (float*)(sm + OCB + 768);                // 64 floats
    float* red = (float*)(sm + OCB + 1024);               // 512 floats (ends OCB+3072)

    const int e   = blockIdx.x;
    const int m0  = blockIdx.y * TMX;
    const int tid = threadIdx.x;
    const int lane = tid & 31;
    const int w    = tid >> 5;
    const int wm   = w & 7;    // 8 row groups of 32
    const int wn   = w >> 3;   // 2 col halves of 64

    if (tid < 128) b1s[tid] = g_eb1eff[e * HH1 + tid];
    if (tid >= 128 && tid < 192) b2s[tid - 128] = eb2[e * HH2 + tid - 128];
    if (tid >= 192 && tid < 256) w3s[tid - 192] = eW3[e * HH2 + tid - 192];

    auto issue = [&](int c) {
        int s = c % 3;
        char* XB = sm + OXB + s * 20480;
        char* WB = sm + OWB + s * 8704;
#pragma unroll
        for (int k = 0; k < 2; ++k) {
            int o = tid + k * 512, r = o >> 2, cg = (o & 3) * 8;
            cp16(XB + (r * 40 + cg) * 2, g_xb + (size_t)(m0 + r) * DD + c * 32 + cg);
        }
        int kr = tid >> 4, cc = (tid & 15) * 8;
        cp16(WB + (kr * 136 + cc) * 2,
             g_eW1b + ((size_t)e * DD + c * 32 + kr) * HH1 + cc);
    };
    auto issueW2 = [&]() {
#pragma unroll
        for (int k = 0; k < 2; ++k) {
            int o = tid + k * 512, kr = o >> 3, cc = (o & 7) * 8;
            cp16((char*)W2s + (kr * 72 + cc) * 2,
                 g_eW2b + (size_t)e * HH1 * HH2 + kr * HH2 + cc);
        }
    };

    issueW2(); issue(0); cp_commit();
    issue(1); cp_commit();

    float acc[2][8][4];
#pragma unroll
    for (int a = 0; a < 2; ++a)
#pragma unroll
        for (int bq = 0; bq < 8; ++bq)
#pragma unroll
            for (int cq = 0; cq < 4; ++cq) acc[a][bq][cq] = 0.f;

    for (int c = 0; c < NCH1; ++c) {
        if (c == NCH1 - 1) cp_wait<0>(); else cp_wait<1>();
        __syncthreads();
        if (c + 2 < NCH1) issue(c + 2);
        cp_commit();
        int s = c % 3;
        const char* XB = sm + OXB + s * 20480;
        const char* WB = sm + OWB + s * 8704;
#pragma unroll
        for (int kk = 0; kk < 2; ++kk) {
            unsigned a0[4], a1[4];
            int ar = wm * 32 + (lane & 15), ac = kk * 16 + (lane >> 4) * 8;
            ldm_x4(a0, cvta_s(XB + (ar * 40 + ac) * 2));
            ldm_x4(a1, cvta_s(XB + ((ar + 16) * 40 + ac) * 2));
            int br = kk * 16 + (lane & 15);
#pragma unroll
            for (int p = 0; p < 4; ++p) {
                unsigned bb[4];
                ldm_x4t(bb, cvta_s(WB + (br * 136 + wn * 64 + p * 16 + (lane >> 4) * 8) * 2));
                mma16816(acc[0][2 * p],     a0, bb[0], bb[1]);
                mma16816(acc[1][2 * p],     a1, bb[0], bb[1]);
                mma16816(acc[0][2 * p + 1], a0, bb[2], bb[3]);
                mma16816(acc[1][2 * p + 1], a1, bb[2], bb[3]);
            }
        }
    }
    __syncthreads();   // stage buffers -> H1 region reuse

    // epilogue GEMM1: bias+relu -> bf16 H1s
#pragma unroll
    for (int mi = 0; mi < 2; ++mi)
#pragma unroll
        for (int nj = 0; nj < 8; ++nj) {
            int r = wm * 32 + mi * 16 + (lane >> 2);
            int c = wn * 64 + nj * 8 + (lane & 3) * 2;
            float ba = b1s[c], bbv = b1s[c + 1];
            float v0 = fmaxf(acc[mi][nj][0] + ba,  0.f);
            float v1 = fmaxf(acc[mi][nj][1] + bbv, 0.f);
            float v2 = fmaxf(acc[mi][nj][2] + ba,  0.f);
            float v3 = fmaxf(acc[mi][nj][3] + bbv, 0.f);
            *(__nv_bfloat162*)(H1s + r * 136 + c)       = __floats2bfloat162_rn(v0, v1);
            *(__nv_bfloat162*)(H1s + (r + 8) * 136 + c) = __floats2bfloat162_rn(v2, v3);
        }
    __syncthreads();

    // GEMM2: H1[256x128] @ W2[128x64] (all resident in smem)
    float acc2[2][4][4];
#pragma unroll
    for (int a = 0; a < 2; ++a)
#pragma unroll
        for (int bq = 0; bq < 4; ++bq)
#pragma unroll
            for (int cq = 0; cq < 4; ++cq) acc2[a][bq][cq] = 0.f;

#pragma unroll
    for (int ch = 0; ch < 4; ++ch)
#pragma unroll
        for (int kk = 0; kk < 2; ++kk) {
            unsigned a0[4], a1[4];
            int ar = wm * 32 + (lane & 15), ac = ch * 32 + kk * 16 + (lane >> 4) * 8;
            ldm_x4(a0, cvta_s(H1s + ar * 136 + ac));
            ldm_x4(a1, cvta_s(H1s + (ar + 16) * 136 + ac));
            int br = ch * 32 + kk * 16 + (lane & 15);
#pragma unroll
            for (int p = 0; p < 2; ++p) {
                unsigned bb[4];
                ldm_x4t(bb, cvta_s(W2s + br * 72 + wn * 32 + p * 16 + (lane >> 4) * 8));
                mma16816(acc2[0][2 * p],     a0, bb[0], bb[1]);
                mma16816(acc2[1][2 * p],     a1, bb[0], bb[1]);
                mma16816(acc2[0][2 * p + 1], a0, bb[2], bb[3]);
                mma16816(acc2[1][2 * p + 1], a1, bb[2], bb[3]);
            }
        }

    // epilogue GEMM2 + GEMM3 dot, all in registers
    float sd[4] = {0.f, 0.f, 0.f, 0.f};   // rows: wm*32 + mi*16 + hh*8 + (lane>>2)
#pragma unroll
    for (int mi = 0; mi < 2; ++mi)
#pragma unroll
        for (int nj = 0; nj < 4; ++nj) {
            int c = wn * 32 + nj * 8 + (lane & 3) * 2;
            float w0 = w3s[c], w1 = w3s[c + 1];
            float ba = b2s[c], bbv = b2s[c + 1];
            sd[mi * 2 + 0] += fmaxf(acc2[mi][nj][0] + ba,  0.f) * w0
                            + fmaxf(acc2[mi][nj][1] + bbv, 0.f) * w1;
            sd[mi * 2 + 1] += fmaxf(acc2[mi][nj][2] + ba,  0.f) * w0
                            + fmaxf(acc2[mi][nj][3] + bbv, 0.f) * w1;
        }
#pragma unroll
    for (int q = 0; q < 4; ++q) {
        sd[q] += __shfl_xor_sync(0xffffffffu, sd[q], 1);
        sd[q] += __shfl_xor_sync(0xffffffffu, sd[q], 2);
    }
    if ((lane & 3) == 0) {
#pragma unroll
        for (int q = 0; q < 4; ++q) {
            int r = wm * 32 + (q >> 1) * 16 + (q & 1) * 8 + (lane >> 2);
            red[wn * 256 + r] = sd[q];
        }
    }
    __syncthreads();
    if (tid < 256) {
        float z = red[tid] + red[256 + tid] + __ldg(eb3 + e);
        out[(size_t)BN * 17 + (size_t)(m0 + tid) * EE + e] = 1.f / (1.f + expf(-z));
    }
}

// ---------------- router kernel ----------------
__global__ void __launch_bounds__(256) router_kernel(const float* __restrict__ rW2,
                                                     const float* __restrict__ rb2,
                                                     const float* __restrict__ rW3,
                                                     const float* __restrict__ rb3,
                                                     float* __restrict__ out) {
    __shared__ __align__(16) char sm[45248];
    __nv_bfloat16* Xb0 = (__nv_bfloat16*)sm;
    __nv_bfloat16* Xb1 = (__nv_bfloat16*)(sm + 10240);
    __nv_bfloat16* Wr0 = (__nv_bfloat16*)(sm + 20480);
    __nv_bfloat16* Wr1 = (__nv_bfloat16*)(sm + 25088);
    float* H1r  = (float*)sm;
    float* rW2s = (float*)(sm + 34816);
    float* rW3s = (float*)(sm + 43008);
    float* rb2s = (float*)(sm + 45056);
    float* rb3s = (float*)(sm + 45184);

    const int m0 = blockIdx.x * 128;
    const int tid = threadIdx.x;
    const int lane = tid & 31;
    const int w = tid >> 5;
    const int wm = w & 3;
    const int wn = w >> 2;

    for (int i = tid; i < RR1 * RR2; i += 256) rW2s[i] = rW2[i];
    for (int i = tid; i < RR2 * EE;  i += 256) rW3s[i] = rW3[i];
    if (tid < RR2) rb2s[tid] = rb2[tid];
    if (tid < EE)  rb3s[tid] = rb3[tid];

    const __nv_bfloat16* Xp = g_xb + (size_t)m0 * DD;
    const int x_r = tid >> 2, x_c = (tid & 3) * 8;
    const int r_r = tid >> 3, r_c = (tid & 7) * 8;

    __nv_bfloat16* XB[2] = {Xb0, Xb1};
    __nv_bfloat16* WB[2] = {Wr0, Wr1};

    auto issue = [&](int c, int b) {
        const __nv_bfloat16* xs = Xp + (size_t)x_r * DD + c * 32 + x_c;
        cp16(XB[b] + x_r * 40 + x_c, xs);
        cp16(XB[b] + (x_r + 64) * 40 + x_c, xs + (size_t)64 * DD);
        cp16(WB[b] + r_r * 72 + r_c, g_rW1b + (c * 32 + r_r) * RR1 + r_c);
    };

    float acc[2][4][4];
#pragma unroll
    for (int a = 0; a < 2; ++a)
#pragma unroll
        for (int bq = 0; bq < 4; ++bq)
#pragma unroll
            for (int cq = 0; cq < 4; ++cq) acc[a][bq][cq] = 0.f;

    issue(0, 0); cp_commit();
    issue(1, 1); cp_commit();
    for (int c = 0; c < DD / 32; ++c) {
        cp_wait<1>(); __syncthreads();
        int b = c & 1;
#pragma unroll
        for (int kk = 0; kk < 2; ++kk) {
            unsigned a0[4], a1[4];
            int ar = wm * 32 + (lane & 15), ac = kk * 16 + (lane >> 4) * 8;
            ldm_x4(a0, cvta_s(XB[b] + ar * 40 + ac));
            ldm_x4(a1, cvta_s(XB[b] + (ar + 16) * 40 + ac));
            int br = kk * 16 + (lane & 15);
#pragma unroll
            for (int p = 0; p < 2; ++p) {
                unsigned bb[4];
                ldm_x4t(bb, cvta_s(WB[b] + br * 72 + wn * 32 + p * 16 + (lane >> 4) * 8));
                mma16816(acc[0][2 * p],     a0, bb[0], bb[1]);
                mma16816(acc[1][2 * p],     a1, bb[0], bb[1]);
                mma16816(acc[0][2 * p + 1], a0, bb[2], bb[3]);
                mma16816(acc[1][2 * p + 1], a1, bb[2], bb[3]);
            }
        }
        __syncthreads();
        if (c + 2 < DD / 32) issue(c + 2, b);
        cp_commit();
    }

#pragma unroll
    for (int mi = 0; mi < 2; ++mi)
#pragma unroll
        for (int nj = 0; nj < 4; ++nj) {
            int r = wm * 32 + mi * 16 + (lane >> 2);
            int c = wn * 32 + nj * 8 + (lane & 3) * 2;
            float ba = g_rb1eff[c], bbv = g_rb1eff[c + 1];
            H1r[r * 67 + c]           = fmaxf(acc[mi][nj][0] + ba,  0.f);
            H1r[r * 67 + c + 1]       = fmaxf(acc[mi][nj][1] + bbv, 0.f);
            H1r[(r + 8) * 67 + c]     = fmaxf(acc[mi][nj][2] + ba,  0.f);
            H1r[(r + 8) * 67 + c + 1] = fmaxf(acc[mi][nj][3] + bbv, 0.f);
        }
    __syncthreads();

    if (tid < 128) {
        const float* h1 = H1r + tid * 67;
        float h2[RR2];
#pragma unroll 4
        for (int j = 0; j < RR2; ++j) {
            float s = rb2s[j];
            for (int i = 0; i < RR1; ++i) s += h1[i] * rW2s[i * RR2 + j];
            h2[j] = fmaxf(s, 0.f);
        }
        float lg[EE];
#pragma unroll
        for (int t = 0; t < EE; ++t) {
            float s = rb3s[t];
#pragma unroll
            for (int j = 0; j < RR2; ++j) s += h2[j] * rW3s[j * EE + t];
            lg[t] = s;
        }
        float mx = lg[0];
#pragma unroll
        for (int t = 1; t < EE; ++t) mx = fmaxf(mx, lg[t]);
        float ex[EE]; float den = 0.f;
#pragma unroll
        for (int t = 0; t < EE; ++t) { ex[t] = expf(lg[t] - mx); den += ex[t]; }
        float inv = 1.f / den;
        float* o = out + BN + (size_t)(m0 + tid) * EE;
#pragma unroll
        for (int t = 0; t < EE; ++t) o[t] = ex[t] * inv;
    }
}

// ---------------- combine ----------------
__global__ void combine_kernel(float* __restrict__ out) {
    int i = blockIdx.x * 256 + threadIdx.x;
    const float4* rw = (const float4*)(out + BN + (size_t)i * EE);
    const float4* eo = (const float4*)(out + (size_t)BN * 17 + (size_t)i * EE);
    float s = 0.f;
#pragma unroll
    for (int q = 0; q < 4; ++q) {
        float4 a = rw[q], b = eo[q];
        s += a.x * b.x + a.y * b.y + a.z * b.z + a.w * b.w;
    }
    out[i] = s;
}

// ---------------- launcher ----------------
extern "C" void kernel_launch(void* const* d_in, const int* in_sizes, int n_in,
                              void* d_out, int out_size) {
    const float* x       = (const float*)d_in[0];
    const float* r_gamma = (const float*)d_in[1];
    const float* r_beta  = (const float*)d_in[2];
    const float* r_mean  = (const float*)d_in[3];
    const float* r_var   = (const float*)d_in[4];
    const float* rW1     = (const float*)d_in[5];
    const float* rb1     = (const float*)d_in[6];
    const float* rW2     = (const float*)d_in[7];
    const float* rb2     = (const float*)d_in[8];
    const float* rW3     = (const float*)d_in[9];
    const float* rb3     = (const float*)d_in[10];
    const float* e_gamma = (const float*)d_in[11];
    const float* e_beta  = (const float*)d_in[12];
    const float* e_mean  = (const float*)d_in[13];
    const float* e_var   = (const float*)d_in[14];
    const float* eW1     = (const float*)d_in[15];
    const float* eb1     = (const float*)d_in[16];
    const float* eW2     = (const float*)d_in[17];
    const float* eb2     = (const float*)d_in[18];
    const float* eW3     = (const float*)d_in[19];
    const float* eb3     = (const float*)d_in[20];
    float* out = (float*)d_out;

    cudaFuncSetAttribute(expert_kernel, cudaFuncAttributeMaxDynamicSharedMemorySize,
                         SMEM_TOT);

    k_conv_x<<<(BN * (size_t)DD) / (256 * 8), 256>>>(x);                              // 0
    k_prep_router<<<320, 256>>>(rW1, r_gamma, r_beta, r_mean, r_var, rb1);            // 1
    k_prep_expert<<<10752, 256>>>(eW1, e_gamma, e_var, eW2, e_beta, e_mean, eb1);     // 2
    expert_kernel<<<dim3(EE, BN / TMX), 512, SMEM_TOT>>>(eb2, eW3, eb3, out);         // 3 (profiled)
    router_kernel<<<BN / 128, 256>>>(rW2, rb2, rW3, rb3, out);                        // 4
    combine_kernel<<<BN / 256, 256>>>(out);                                           // 5
}

// round 12
// speedup vs baseline: 1.1332x; 1.1332x over previous
#include <cuda_runtime.h>
#include <cuda_bf16.h>
#include <math.h>
#include <stdint.h>

#define BN 65536
#define DD 1024
#define EE 16
#define HH1 128
#define HH2 64
#define RR1 64
#define RR2 32
#define EPSV 1e-5f

// fused kernel: 128 rows x (1 expert | router) per CTA, 256 threads, 2 CTAs/SM
#define TMX 128
#define NCH1 32          // K chunks of 32

// dynamic smem map (expert path)
#define OXB 0            // 3 stages x 10240 (128 x 40 halves)
#define OWB 30720        // 3 stages x 8704  (32 x 136 halves)
#define OW2 56832        // 128 x 72 halves = 18432
#define OCB 75264        // b1s 512 | b2s 256 | w3s 256 | red 1024
#define SMEM_TOT 77824

// ---------------- device scratch ----------------
__device__ __nv_bfloat16 g_xb[(size_t)BN * DD];
__device__ __nv_bfloat16 g_rW1b[DD * RR1];
__device__ float         g_rb1eff[RR1];
__device__ __nv_bfloat16 g_eW1b[(size_t)EE * DD * HH1];   // [e][d][h] folded
__device__ float         g_eb1eff[EE * HH1];
__device__ __nv_bfloat16 g_eW2b[EE * HH1 * HH2];          // [e][h][j]

// ---------------- helpers ----------------
__device__ __forceinline__ unsigned cvta_s(const void* p) {
    return (unsigned)__cvta_generic_to_shared(p);
}
__device__ __forceinline__ void cp16(void* s, const void* g) {
    asm volatile("cp.async.cg.shared.global [%0], [%1], 16;\n"
                 :: "r"(cvta_s(s)), "l"(g));
}
__device__ __forceinline__ void cp_commit() {
    asm volatile("cp.async.commit_group;\n");
}
template<int N> __device__ __forceinline__ void cp_wait() {
    asm volatile("cp.async.wait_group %0;\n" :: "n"(N));
}
__device__ __forceinline__ void ldm_x4(unsigned r[4], unsigned addr) {
    asm volatile("ldmatrix.sync.aligned.m8n8.x4.shared.b16 {%0,%1,%2,%3}, [%4];"
                 : "=r"(r[0]), "=r"(r[1]), "=r"(r[2]), "=r"(r[3]) : "r"(addr));
}
__device__ __forceinline__ void ldm_x4t(unsigned r[4], unsigned addr) {
    asm volatile("ldmatrix.sync.aligned.m8n8.x4.trans.shared.b16 {%0,%1,%2,%3}, [%4];"
                 : "=r"(r[0]), "=r"(r[1]), "=r"(r[2]), "=r"(r[3]) : "r"(addr));
}
__device__ __forceinline__ void mma16816(float d[4], const unsigned a[4],
                                         unsigned b0, unsigned b1) {
    asm volatile(
        "mma.sync.aligned.m16n8k16.row.col.f32.bf16.bf16.f32 "
        "{%0,%1,%2,%3}, {%4,%5,%6,%7}, {%8,%9}, {%0,%1,%2,%3};"
        : "+f"(d[0]), "+f"(d[1]), "+f"(d[2]), "+f"(d[3])
        : "r"(a[0]), "r"(a[1]), "r"(a[2]), "r"(a[3]), "r"(b0), "r"(b1));
}
__device__ __forceinline__ unsigned packbf(float a, float b) {
    __nv_bfloat162 t = __floats2bfloat162_rn(a, b);
    return *reinterpret_cast<unsigned*>(&t);
}

// ---------------- prep kernels ----------------
__global__ void k_conv_x(const float* __restrict__ x) {
    size_t i = ((size_t)blockIdx.x * 256 + threadIdx.x) * 8;
    float4 v0 = *(const float4*)(x + i);
    float4 v1 = *(const float4*)(x + i + 4);
    uint4 u;
    u.x = packbf(v0.x, v0.y); u.y = packbf(v0.z, v0.w);
    u.z = packbf(v1.x, v1.y); u.w = packbf(v1.z, v1.w);
    *(uint4*)(g_xb + i) = u;
}

__global__ void k_prep_router(const float* __restrict__ rW1, const float* __restrict__ g,
                              const float* __restrict__ be, const float* __restrict__ mn,
                              const float* __restrict__ v, const float* __restrict__ rb1) {
    int b = blockIdx.x, t = threadIdx.x;
    if (b < 256) {
        int i = b * 256 + t;
        int d = i >> 6;
        float rs = g[d] * rsqrtf(v[d] + EPSV);
        g_rW1b[i] = __float2bfloat16(rW1[i] * rs);
    } else {
        int h = b - 256;
        float s = 0.f;
        for (int d = t; d < DD; d += 256) {
            float rs = g[d] * rsqrtf(v[d] + EPSV);
            float sh = be[d] - mn[d] * rs;
            s += sh * rW1[d * RR1 + h];
        }
        __shared__ float red[256];
        red[t] = s; __syncthreads();
        for (int o = 128; o; o >>= 1) { if (t < o) red[t] += red[t + o]; __syncthreads(); }
        if (!t) g_rb1eff[h] = rb1[h] + red[0];
    }
}

// [0,8192): fold eW1 -> bf16; [8192,8704): conv eW2; [8704,10752): fold bias
__global__ void k_prep_expert(const float* __restrict__ eW1, const float* __restrict__ g,
                              const float* __restrict__ v, const float* __restrict__ eW2,
                              const float* __restrict__ be, const float* __restrict__ mn,
                              const float* __restrict__ eb1) {
    int b = blockIdx.x, t = threadIdx.x;
    if (b < 8192) {
        int i = b * 256 + t;
        int ed = i >> 7;
        float sc = g[ed] * rsqrtf(v[ed] + EPSV);
        g_eW1b[i] = __float2bfloat16(eW1[i] * sc);
    } else if (b < 8704) {
        int i = (b - 8192) * 256 + t;
        g_eW2b[i] = __float2bfloat16(eW2[i]);
    } else {
        int bb = b - 8704;
        int e = bb >> 7, h = bb & 127;
        float s = 0.f;
        for (int d = t; d < DD; d += 256) {
            int ed = e * DD + d;
            float sc = g[ed] * rsqrtf(v[ed] + EPSV);
            float sh = be[ed] - mn[ed] * sc;
            s += sh * eW1[(size_t)ed * HH1 + h];
        }
        __shared__ float red[256];
        red[t] = s; __syncthreads();
        for (int o = 128; o; o >>= 1) { if (t < o) red[t] += red[t + o]; __syncthreads(); }
        if (!t) g_eb1eff[bb] = eb1[bb] + red[0];
    }
}

// ---------------- fused kernel: blockIdx.x<16 -> expert e; ==16 -> router ----------------
__global__ void __launch_bounds__(256, 2)
fused_kernel(const float* __restrict__ eb2, const float* __restrict__ eW3,
             const float* __restrict__ eb3,
             const float* __restrict__ rW2, const float* __restrict__ rb2,
             const float* __restrict__ rW3, const float* __restrict__ rb3,
             float* __restrict__ out) {
    extern __shared__ __align__(16) char sm[];
    const int m0  = blockIdx.y * TMX;
    const int tid = threadIdx.x;
    const int lane = tid & 31;
    const int w    = tid >> 5;

    if (blockIdx.x < EE) {
        // ================= EXPERT PATH =================
        __nv_bfloat16* H1s = (__nv_bfloat16*)sm;              // [128][136], overlaps stages
        __nv_bfloat16* W2s = (__nv_bfloat16*)(sm + OW2);      // [128][72]
        float* b1s = (float*)(sm + OCB);                      // 128 floats
        float* b2s = (float*)(sm + OCB + 512);                // 64 floats
        float* w3s = (float*)(sm + OCB + 768);                // 64 floats
        float* red = (float*)(sm + OCB + 1024);               // 256 floats

        const int e  = blockIdx.x;
        const int wm = w & 3;    // 4 row groups of 32
        const int wn = w >> 2;   // 2 col halves of 64

        if (tid < 128) b1s[tid] = g_eb1eff[e * HH1 + tid];
        if (tid >= 128 && tid < 192) b2s[tid - 128] = eb2[e * HH2 + tid - 128];
        if (tid >= 192) w3s[tid - 192] = eW3[e * HH2 + tid - 192];

        auto issue = [&](int c) {
            int s = c % 3;
            char* XB = sm + OXB + s * 10240;
            char* WB = sm + OWB + s * 8704;
            int xr = tid >> 2, xc = (tid & 3) * 8;
            const __nv_bfloat16* xs = g_xb + (size_t)(m0 + xr) * DD + c * 32 + xc;
            cp16(XB + (xr * 40 + xc) * 2, xs);
            cp16(XB + ((xr + 64) * 40 + xc) * 2, xs + (size_t)64 * DD);
            int kr = tid >> 4, cc = (tid & 15) * 8;
            const __nv_bfloat16* ws = g_eW1b + ((size_t)e * DD + c * 32 + kr) * HH1 + cc;
            cp16(WB + (kr * 136 + cc) * 2, ws);
            cp16(WB + ((kr + 16) * 136 + cc) * 2, ws + (size_t)16 * HH1);
        };
        auto issueW2 = [&]() {
#pragma unroll
            for (int k = 0; k < 4; ++k) {
                int o = tid + k * 256, kr = o >> 3, cc = (o & 7) * 8;
                cp16((char*)W2s + (kr * 72 + cc) * 2,
                     g_eW2b + (size_t)e * HH1 * HH2 + kr * HH2 + cc);
            }
        };

        issueW2(); issue(0); cp_commit();
        issue(1); cp_commit();

        float acc[2][8][4];
#pragma unroll
        for (int a = 0; a < 2; ++a)
#pragma unroll
            for (int bq = 0; bq < 8; ++bq)
#pragma unroll
                for (int cq = 0; cq < 4; ++cq) acc[a][bq][cq] = 0.f;

        for (int c = 0; c < NCH1; ++c) {
            if (c == NCH1 - 1) cp_wait<0>(); else cp_wait<1>();
            __syncthreads();
            if (c + 2 < NCH1) issue(c + 2);
            cp_commit();
            int s = c % 3;
            const char* XB = sm + OXB + s * 10240;
            const char* WB = sm + OWB + s * 8704;
#pragma unroll
            for (int kk = 0; kk < 2; ++kk) {
                unsigned a0[4], a1[4];
                int ar = wm * 32 + (lane & 15), ac = kk * 16 + (lane >> 4) * 8;
                ldm_x4(a0, cvta_s(XB + (ar * 40 + ac) * 2));
                ldm_x4(a1, cvta_s(XB + ((ar + 16) * 40 + ac) * 2));
                int br = kk * 16 + (lane & 15);
#pragma unroll
                for (int p = 0; p < 4; ++p) {
                    unsigned bb[4];
                    ldm_x4t(bb, cvta_s(WB + (br * 136 + wn * 64 + p * 16 + (lane >> 4) * 8) * 2));
                    mma16816(acc[0][2 * p],     a0, bb[0], bb[1]);
                    mma16816(acc[1][2 * p],     a1, bb[0], bb[1]);
                    mma16816(acc[0][2 * p + 1], a0, bb[2], bb[3]);
                    mma16816(acc[1][2 * p + 1], a1, bb[2], bb[3]);
                }
            }
        }
        __syncthreads();   // stage buffers -> H1 region reuse

        // epilogue GEMM1: bias+relu -> bf16 H1s
#pragma unroll
        for (int mi = 0; mi < 2; ++mi)
#pragma unroll
            for (int nj = 0; nj < 8; ++nj) {
                int r = wm * 32 + mi * 16 + (lane >> 2);
                int c = wn * 64 + nj * 8 + (lane & 3) * 2;
                float ba = b1s[c], bbv = b1s[c + 1];
                float v0 = fmaxf(acc[mi][nj][0] + ba,  0.f);
                float v1 = fmaxf(acc[mi][nj][1] + bbv, 0.f);
                float v2 = fmaxf(acc[mi][nj][2] + ba,  0.f);
                float v3 = fmaxf(acc[mi][nj][3] + bbv, 0.f);
                *(__nv_bfloat162*)(H1s + r * 136 + c)       = __floats2bfloat162_rn(v0, v1);
                *(__nv_bfloat162*)(H1s + (r + 8) * 136 + c) = __floats2bfloat162_rn(v2, v3);
            }
        __syncthreads();

        // GEMM2: H1[128x128] @ W2[128x64] (resident)
        float acc2[2][4][4];
#pragma unroll
        for (int a = 0; a < 2; ++a)
#pragma unroll
            for (int bq = 0; bq < 4; ++bq)
#pragma unroll
                for (int cq = 0; cq < 4; ++cq) acc2[a][bq][cq] = 0.f;

#pragma unroll
        for (int ch = 0; ch < 4; ++ch)
#pragma unroll
            for (int kk = 0; kk < 2; ++kk) {
                unsigned a0[4], a1[4];
                int ar = wm * 32 + (lane & 15), ac = ch * 32 + kk * 16 + (lane >> 4) * 8;
                ldm_x4(a0, cvta_s(H1s + ar * 136 + ac));
                ldm_x4(a1, cvta_s(H1s + (ar + 16) * 136 + ac));
                int br = ch * 32 + kk * 16 + (lane & 15);
#pragma unroll
                for (int p = 0; p < 2; ++p) {
                    unsigned bb[4];
                    ldm_x4t(bb, cvta_s(W2s + br * 72 + wn * 32 + p * 16 + (lane >> 4) * 8));
                    mma16816(acc2[0][2 * p],     a0, bb[0], bb[1]);
                    mma16816(acc2[1][2 * p],     a1, bb[0], bb[1]);
                    mma16816(acc2[0][2 * p + 1], a0, bb[2], bb[3]);
                    mma16816(acc2[1][2 * p + 1], a1, bb[2], bb[3]);
                }
            }

        // epilogue GEMM2 + GEMM3 dot in registers
        float sd[4] = {0.f, 0.f, 0.f, 0.f};
#pragma unroll
        for (int mi = 0; mi < 2; ++mi)
#pragma unroll
            for (int nj = 0; nj < 4; ++nj) {
                int c = wn * 32 + nj * 8 + (lane & 3) * 2;
                float w0 = w3s[c], w1 = w3s[c + 1];
                float ba = b2s[c], bbv = b2s[c + 1];
                sd[mi * 2 + 0] += fmaxf(acc2[mi][nj][0] + ba,  0.f) * w0
                                + fmaxf(acc2[mi][nj][1] + bbv, 0.f) * w1;
                sd[mi * 2 + 1] += fmaxf(acc2[mi][nj][2] + ba,  0.f) * w0
                                + fmaxf(acc2[mi][nj][3] + bbv, 0.f) * w1;
            }
#pragma unroll
        for (int q = 0; q < 4; ++q) {
            sd[q] += __shfl_xor_sync(0xffffffffu, sd[q], 1);
            sd[q] += __shfl_xor_sync(0xffffffffu, sd[q], 2);
        }
        if ((lane & 3) == 0) {
#pragma unroll
            for (int q = 0; q < 4; ++q) {
                int r = wm * 32 + (q >> 1) * 16 + (q & 1) * 8 + (lane >> 2);
                red[wn * 128 + r] = sd[q];
            }
        }
        __syncthreads();
        if (tid < 128) {
            float z = red[tid] + red[128 + tid] + __ldg(eb3 + e);
            out[(size_t)BN * 17 + (size_t)(m0 + tid) * EE + e] = 1.f / (1.f + expf(-z));
        }
    } else {
        // ================= ROUTER PATH =================
        __nv_bfloat16* Xb0 = (__nv_bfloat16*)sm;
        __nv_bfloat16* Xb1 = (__nv_bfloat16*)(sm + 10240);
        __nv_bfloat16* Wr0 = (__nv_bfloat16*)(sm + 20480);
        __nv_bfloat16* Wr1 = (__nv_bfloat16*)(sm + 25088);
        float* H1r  = (float*)sm;
        float* rW2s = (float*)(sm + 34816);
        float* rW3s = (float*)(sm + 43008);
        float* rb2s = (float*)(sm + 45056);
        float* rb3s = (float*)(sm + 45184);

        const int wm = w & 3;
        const int wn = w >> 2;

        for (int i = tid; i < RR1 * RR2; i += 256) rW2s[i] = rW2[i];
        for (int i = tid; i < RR2 * EE;  i += 256) rW3s[i] = rW3[i];
        if (tid < RR2) rb2s[tid] = rb2[tid];
        if (tid < EE)  rb3s[tid] = rb3[tid];

        const __nv_bfloat16* Xp = g_xb + (size_t)m0 * DD;
        const int x_r = tid >> 2, x_c = (tid & 3) * 8;
        const int r_r = tid >> 3, r_c = (tid & 7) * 8;

        __nv_bfloat16* XB[2] = {Xb0, Xb1};
        __nv_bfloat16* WB[2] = {Wr0, Wr1};

        auto issue = [&](int c, int b) {
            const __nv_bfloat16* xs = Xp + (size_t)x_r * DD + c * 32 + x_c;
            cp16(XB[b] + x_r * 40 + x_c, xs);
            cp16(XB[b] + (x_r + 64) * 40 + x_c, xs + (size_t)64 * DD);
            cp16(WB[b] + r_r * 72 + r_c, g_rW1b + (c * 32 + r_r) * RR1 + r_c);
        };

        float acc[2][4][4];
#pragma unroll
        for (int a = 0; a < 2; ++a)
#pragma unroll
            for (int bq = 0; bq < 4; ++bq)
#pragma unroll
                for (int cq = 0; cq < 4; ++cq) acc[a][bq][cq] = 0.f;

        issue(0, 0); cp_commit();
        issue(1, 1); cp_commit();
        for (int c = 0; c < DD / 32; ++c) {
            cp_wait<1>(); __syncthreads();
            int b = c & 1;
#pragma unroll
            for (int kk = 0; kk < 2; ++kk) {
                unsigned a0[4], a1[4];
                int ar = wm * 32 + (lane & 15), ac = kk * 16 + (lane >> 4) * 8;
                ldm_x4(a0, cvta_s(XB[b] + ar * 40 + ac));
                ldm_x4(a1, cvta_s(XB[b] + (ar + 16) * 40 + ac));
                int br = kk * 16 + (lane & 15);
#pragma unroll
                for (int p = 0; p < 2; ++p) {
                    unsigned bb[4];
                    ldm_x4t(bb, cvta_s(WB[b] + br * 72 + wn * 32 + p * 16 + (lane >> 4) * 8));
                    mma16816(acc[0][2 * p],     a0, bb[0], bb[1]);
                    mma16816(acc[1][2 * p],     a1, bb[0], bb[1]);
                    mma16816(acc[0][2 * p + 1], a0, bb[2], bb[3]);
                    mma16816(acc[1][2 * p + 1], a1, bb[2], bb[3]);
                }
            }
            __syncthreads();
            if (c + 2 < DD / 32) issue(c + 2, b);
            cp_commit();
        }

#pragma unroll
        for (int mi = 0; mi < 2; ++mi)
#pragma unroll
            for (int nj = 0; nj < 4; ++nj) {
                int r = wm * 32 + mi * 16 + (lane >> 2);
                int c = wn * 32 + nj * 8 + (lane & 3) * 2;
                float ba = g_rb1eff[c], bbv = g_rb1eff[c + 1];
                H1r[r * 67 + c]           = fmaxf(acc[mi][nj][0] + ba,  0.f);
                H1r[r * 67 + c + 1]       = fmaxf(acc[mi][nj][1] + bbv, 0.f);
                H1r[(r + 8) * 67 + c]     = fmaxf(acc[mi][nj][2] + ba,  0.f);
                H1r[(r + 8) * 67 + c + 1] = fmaxf(acc[mi][nj][3] + bbv, 0.f);
            }
        __syncthreads();

        if (tid < 128) {
            const float* h1 = H1r + tid * 67;
            float h2[RR2];
#pragma unroll 4
            for (int j = 0; j < RR2; ++j) {
                float s = rb2s[j];
                for (int i = 0; i < RR1; ++i) s += h1[i] * rW2s[i * RR2 + j];
                h2[j] = fmaxf(s, 0.f);
            }
            float lg[EE];
#pragma unroll
            for (int t = 0; t < EE; ++t) {
                float s = rb3s[t];
#pragma unroll
                for (int j = 0; j < RR2; ++j) s += h2[j] * rW3s[j * EE + t];
                lg[t] = s;
            }
            float mx = lg[0];
#pragma unroll
            for (int t = 1; t < EE; ++t) mx = fmaxf(mx, lg[t]);
            float ex[EE]; float den = 0.f;
#pragma unroll
            for (int t = 0; t < EE; ++t) { ex[t] = expf(lg[t] - mx); den += ex[t]; }
            float inv = 1.f / den;
            float* o = out + BN + (size_t)(m0 + tid) * EE;
#pragma unroll
            for (int t = 0; t < EE; ++t) o[t] = ex[t] * inv;
        }
    }
}

// ---------------- combine ----------------
__global__ void combine_kernel(float* __restrict__ out) {
    int i = blockIdx.x * 256 + threadIdx.x;
    const float4* rw = (const float4*)(out + BN + (size_t)i * EE);
    const float4* eo = (const float4*)(out + (size_t)BN * 17 + (size_t)i * EE);
    float s = 0.f;
#pragma unroll
    for (int q = 0; q < 4; ++q) {
        float4 a = rw[q], b = eo[q];
        s += a.x * b.x + a.y * b.y + a.z * b.z + a.w * b.w;
    }
    out[i] = s;
}

// ---------------- launcher ----------------
extern "C" void kernel_launch(void* const* d_in, const int* in_sizes, int n_in,
                              void* d_out, int out_size) {
    const float* x       = (const float*)d_in[0];
    const float* r_gamma = (const float*)d_in[1];
    const float* r_beta  = (const float*)d_in[2];
    const float* r_mean  = (const float*)d_in[3];
    const float* r_var   = (const float*)d_in[4];
    const float* rW1     = (const float*)d_in[5];
    const float* rb1     = (const float*)d_in[6];
    const float* rW2     = (const float*)d_in[7];
    const float* rb2     = (const float*)d_in[8];
    const float* rW3     = (const float*)d_in[9];
    const float* rb3     = (const float*)d_in[10];
    const float* e_gamma = (const float*)d_in[11];
    const float* e_beta  = (const float*)d_in[12];
    const float* e_mean  = (const float*)d_in[13];
    const float* e_var   = (const float*)d_in[14];
    const float* eW1     = (const float*)d_in[15];
    const float* eb1     = (const float*)d_in[16];
    const float* eW2     = (const float*)d_in[17];
    const float* eb2     = (const float*)d_in[18];
    const float* eW3     = (const float*)d_in[19];
    const float* eb3     = (const float*)d_in[20];
    float* out = (float*)d_out;

    cudaFuncSetAttribute(fused_kernel, cudaFuncAttributeMaxDynamicSharedMemorySize,
                         SMEM_TOT);

    k_conv_x<<<(BN * (size_t)DD) / (256 * 8), 256>>>(x);                              // 0
    k_prep_router<<<320, 256>>>(rW1, r_gamma, r_beta, r_mean, r_var, rb1);            // 1
    k_prep_expert<<<10752, 256>>>(eW1, e_gamma, e_var, eW2, e_beta, e_mean, eb1);     // 2
    fused_kernel<<<dim3(EE + 1, BN / TMX), 256, SMEM_TOT>>>(                          // 3 (profiled)
        eb2, eW3, eb3, rW2, rb2, rW3, rb3, out);
    combine_kernel<<<BN / 256, 256>>>(out);                                           // 4
}

// round 13
// speedup vs baseline: 1.1849x; 1.0456x over previous
#include <cuda_runtime.h>
#include <cuda_bf16.h>
#include <math.h>
#include <stdint.h>

#define BN 65536
#define DD 1024
#define EE 16
#define HH1 128
#define HH2 64
#define RR1 64
#define RR2 32
#define EPSV 1e-5f

// fused kernel: 128 rows x (1 expert | router) per CTA, 256 threads, 2 CTAs/SM
#define TMX 128

// dynamic smem map (expert path)
#define OXB 0            // 3 stages x 10240 (128 x 40 halves)
#define OWB 30720        // 3 stages x 8704  (32 x 136 halves)
#define OW2 56832        // 128 x 72 halves = 18432
#define OCB 75264        // b1s 512 | b2s 256 | w3s 256 | red 1024
#define SMEM_TOT 77824

// ---------------- device scratch ----------------
__device__ __nv_bfloat16 g_xb[(size_t)BN * DD];
__device__ __nv_bfloat16 g_rW1b[DD * RR1];
__device__ float         g_rb1eff[RR1];
__device__ __nv_bfloat16 g_eW1b[(size_t)EE * DD * HH1];   // [e][d][h] folded
__device__ float         g_eb1eff[EE * HH1];
__device__ __nv_bfloat16 g_eW2b[EE * HH1 * HH2];          // [e][h][j]

// ---------------- helpers ----------------
__device__ __forceinline__ unsigned cvta_s(const void* p) {
    return (unsigned)__cvta_generic_to_shared(p);
}
__device__ __forceinline__ void cp16(void* s, const void* g) {
    asm volatile("cp.async.cg.shared.global [%0], [%1], 16;\n"
                 :: "r"(cvta_s(s)), "l"(g));
}
__device__ __forceinline__ void cp16s(unsigned s, const void* g) {
    asm volatile("cp.async.cg.shared.global [%0], [%1], 16;\n"
                 :: "r"(s), "l"(g));
}
__device__ __forceinline__ void cp_commit() {
    asm volatile("cp.async.commit_group;\n");
}
template<int N> __device__ __forceinline__ void cp_wait() {
    asm volatile("cp.async.wait_group %0;\n" :: "n"(N));
}
__device__ __forceinline__ void ldm_x4(unsigned r[4], unsigned addr) {
    asm volatile("ldmatrix.sync.aligned.m8n8.x4.shared.b16 {%0,%1,%2,%3}, [%4];"
                 : "=r"(r[0]), "=r"(r[1]), "=r"(r[2]), "=r"(r[3]) : "r"(addr));
}
__device__ __forceinline__ void ldm_x4t(unsigned r[4], unsigned addr) {
    asm volatile("ldmatrix.sync.aligned.m8n8.x4.trans.shared.b16 {%0,%1,%2,%3}, [%4];"
                 : "=r"(r[0]), "=r"(r[1]), "=r"(r[2]), "=r"(r[3]) : "r"(addr));
}
__device__ __forceinline__ void mma16816(float d[4], const unsigned a[4],
                                         unsigned b0, unsigned b1) {
    asm volatile(
        "mma.sync.aligned.m16n8k16.row.col.f32.bf16.bf16.f32 "
        "{%0,%1,%2,%3}, {%4,%5,%6,%7}, {%8,%9}, {%0,%1,%2,%3};"
        : "+f"(d[0]), "+f"(d[1]), "+f"(d[2]), "+f"(d[3])
        : "r"(a[0]), "r"(a[1]), "r"(a[2]), "r"(a[3]), "r"(b0), "r"(b1));
}
__device__ __forceinline__ unsigned packbf(float a, float b) {
    __nv_bfloat162 t = __floats2bfloat162_rn(a, b);
    return *reinterpret_cast<unsigned*>(&t);
}

// ---------------- prep kernels ----------------
__global__ void k_conv_x(const float* __restrict__ x) {
    size_t i = ((size_t)blockIdx.x * 256 + threadIdx.x) * 8;
    float4 v0 = *(const float4*)(x + i);
    float4 v1 = *(const float4*)(x + i + 4);
    uint4 u;
    u.x = packbf(v0.x, v0.y); u.y = packbf(v0.z, v0.w);
    u.z = packbf(v1.x, v1.y); u.w = packbf(v1.z, v1.w);
    *(uint4*)(g_xb + i) = u;
}

__global__ void k_prep_router(const float* __restrict__ rW1, const float* __restrict__ g,
                              const float* __restrict__ be, const float* __restrict__ mn,
                              const float* __restrict__ v, const float* __restrict__ rb1) {
    int b = blockIdx.x, t = threadIdx.x;
    if (b < 256) {
        int i = b * 256 + t;
        int d = i >> 6;
        float rs = g[d] * rsqrtf(v[d] + EPSV);
        g_rW1b[i] = __float2bfloat16(rW1[i] * rs);
    } else {
        int h = b - 256;
        float s = 0.f;
        for (int d = t; d < DD; d += 256) {
            float rs = g[d] * rsqrtf(v[d] + EPSV);
            float sh = be[d] - mn[d] * rs;
            s += sh * rW1[d * RR1 + h];
        }
        __shared__ float red[256];
        red[t] = s; __syncthreads();
        for (int o = 128; o; o >>= 1) { if (t < o) red[t] += red[t + o]; __syncthreads(); }
        if (!t) g_rb1eff[h] = rb1[h] + red[0];
    }
}

// [0,8192): fold eW1 -> bf16; [8192,8704): conv eW2; [8704,10752): fold bias
__global__ void k_prep_expert(const float* __restrict__ eW1, const float* __restrict__ g,
                              const float* __restrict__ v, const float* __restrict__ eW2,
                              const float* __restrict__ be, const float* __restrict__ mn,
                              const float* __restrict__ eb1) {
    int b = blockIdx.x, t = threadIdx.x;
    if (b < 8192) {
        int i = b * 256 + t;
        int ed = i >> 7;
        float sc = g[ed] * rsqrtf(v[ed] + EPSV);
        g_eW1b[i] = __float2bfloat16(eW1[i] * sc);
    } else if (b < 8704) {
        int i = (b - 8192) * 256 + t;
        g_eW2b[i] = __float2bfloat16(eW2[i]);
    } else {
        int bb = b - 8704;
        int e = bb >> 7, h = bb & 127;
        float s = 0.f;
        for (int d = t; d < DD; d += 256) {
            int ed = e * DD + d;
            float sc = g[ed] * rsqrtf(v[ed] + EPSV);
            float sh = be[ed] - mn[ed] * sc;
            s += sh * eW1[(size_t)ed * HH1 + h];
        }
        __shared__ float red[256];
        red[t] = s; __syncthreads();
        for (int o = 128; o; o >>= 1) { if (t < o) red[t] += red[t + o]; __syncthreads(); }
        if (!t) g_eb1eff[bb] = eb1[bb] + red[0];
    }
}

// ---------------- fused kernel: blockIdx.x<16 -> expert e; ==16 -> router ----------------
__global__ void __launch_bounds__(256, 2)
fused_kernel(const float* __restrict__ eb2, const float* __restrict__ eW3,
             const float* __restrict__ eb3,
             const float* __restrict__ rW2, const float* __restrict__ rb2,
             const float* __restrict__ rW3, const float* __restrict__ rb3,
             float* __restrict__ out) {
    extern __shared__ __align__(16) char sm[];
    const int m0  = blockIdx.y * TMX;
    const int tid = threadIdx.x;
    const int lane = tid & 31;
    const int w    = tid >> 5;

    if (blockIdx.x < EE) {
        // ================= EXPERT PATH =================
        __nv_bfloat16* H1s = (__nv_bfloat16*)sm;              // [128][136], overlaps stages
        __nv_bfloat16* W2s = (__nv_bfloat16*)(sm + OW2);      // [128][72]
        float* b1s = (float*)(sm + OCB);                      // 128 floats
        float* b2s = (float*)(sm + OCB + 512);                // 64 floats
        float* w3s = (float*)(sm + OCB + 768);                // 64 floats
        float* red = (float*)(sm + OCB + 1024);               // 256 floats

        const int e  = blockIdx.x;
        const int wm = w & 3;    // 4 row groups of 32
        const int wn = w >> 2;   // 2 col halves of 64

        if (tid < 128) b1s[tid] = g_eb1eff[e * HH1 + tid];
        if (tid >= 128 && tid < 192) b2s[tid - 128] = eb2[e * HH2 + tid - 128];
        if (tid >= 192) w3s[tid - 192] = eW3[e * HH2 + tid - 192];

        const unsigned sb = cvta_s(sm);

        // ---- hoisted cp.async destinations (per-stage = + s*const) ----
        const int xr = tid >> 2, xc = (tid & 3) * 8;
        const int kr = tid >> 4, kc = (tid & 15) * 8;
        const unsigned xd0 = sb + OXB + (xr * 40 + xc) * 2;
        const unsigned xd1 = sb + OXB + ((xr + 64) * 40 + xc) * 2;
        const unsigned wd0 = sb + OWB + (kr * 136 + kc) * 2;
        const unsigned wd1 = sb + OWB + ((kr + 16) * 136 + kc) * 2;
        // ---- running global source pointers ----
        const __nv_bfloat16* xs0 = g_xb + (size_t)(m0 + xr) * DD + xc;
        const __nv_bfloat16* xs1 = xs0 + (size_t)64 * DD;
        const __nv_bfloat16* ws0 = g_eW1b + ((size_t)e * DD + kr) * HH1 + kc;
        const __nv_bfloat16* ws1 = ws0 + 16 * HH1;

        auto issue = [&](const int s) {   // s is a compile-time literal at every call site
            cp16s(xd0 + s * 10240, xs0);
            cp16s(xd1 + s * 10240, xs1);
            cp16s(wd0 + s * 8704,  ws0);
            cp16s(wd1 + s * 8704,  ws1);
            xs0 += 32; xs1 += 32; ws0 += 32 * HH1; ws1 += 32 * HH1;
        };
        auto issueW2 = [&]() {
#pragma unroll
            for (int k = 0; k < 4; ++k) {
                int o = tid + k * 256, r2 = o >> 3, c2 = (o & 7) * 8;
                cp16((char*)W2s + (r2 * 72 + c2) * 2,
                     g_eW2b + (size_t)e * HH1 * HH2 + r2 * HH2 + c2);
            }
        };

        // ---- hoisted ldmatrix bases (per-warp constants) ----
        const int a_r = wm * 32 + (lane & 15);
        const unsigned aB = sb + OXB + (a_r * 40 + (lane >> 4) * 8) * 2;   // +kk*32, +1280 (16 rows)
        const unsigned bB = sb + OWB + ((lane & 15) * 136 + wn * 64 + (lane >> 4) * 8) * 2; // +kk*4352, +p*32

        float acc[2][8][4];
#pragma unroll
        for (int a = 0; a < 2; ++a)
#pragma unroll
            for (int bq = 0; bq < 8; ++bq)
#pragma unroll
                for (int cq = 0; cq < 4; ++cq) acc[a][bq][cq] = 0.f;

        auto compute = [&](const int s) {  // s literal -> all addresses fold to base+imm
#pragma unroll
            for (int kk = 0; kk < 2; ++kk) {
                unsigned a0[4], a1[4];
                ldm_x4(a0, aB + s * 10240 + kk * 32);
                ldm_x4(a1, aB + s * 10240 + kk * 32 + 1280);
#pragma unroll
                for (int p = 0; p < 4; ++p) {
                    unsigned bb[4];
                    ldm_x4t(bb, bB + s * 8704 + kk * 4352 + p * 32);
                    mma16816(acc[0][2 * p],     a0, bb[0], bb[1]);
                    mma16816(acc[1][2 * p],     a1, bb[0], bb[1]);
                    mma16816(acc[0][2 * p + 1], a0, bb[2], bb[3]);
                    mma16816(acc[1][2 * p + 1], a1, bb[2], bb[3]);
                }
            }
        };

        issueW2(); issue(0); cp_commit();
        issue(1); cp_commit();

        // 32 chunks = 10 x (3 unrolled) + 2 remainder; stage indices are literals
        for (int j = 0; j < 10; ++j) {
            cp_wait<1>(); __syncthreads(); issue(2); cp_commit(); compute(0);
            cp_wait<1>(); __syncthreads(); issue(0); cp_commit(); compute(1);
            cp_wait<1>(); __syncthreads(); issue(1); cp_commit(); compute(2);
        }
        cp_wait<1>(); __syncthreads(); compute(0);   // chunk 30
        cp_wait<0>(); __syncthreads(); compute(1);   // chunk 31
        __syncthreads();   // stage buffers -> H1 region reuse

        // epilogue GEMM1: bias+relu -> bf16 H1s
#pragma unroll
        for (int mi = 0; mi < 2; ++mi)
#pragma unroll
            for (int nj = 0; nj < 8; ++nj) {
                int r = wm * 32 + mi * 16 + (lane >> 2);
                int c = wn * 64 + nj * 8 + (lane & 3) * 2;
                float ba = b1s[c], bbv = b1s[c + 1];
                float v0 = fmaxf(acc[mi][nj][0] + ba,  0.f);
                float v1 = fmaxf(acc[mi][nj][1] + bbv, 0.f);
                float v2 = fmaxf(acc[mi][nj][2] + ba,  0.f);
                float v3 = fmaxf(acc[mi][nj][3] + bbv, 0.f);
                *(__nv_bfloat162*)(H1s + r * 136 + c)       = __floats2bfloat162_rn(v0, v1);
                *(__nv_bfloat162*)(H1s + (r + 8) * 136 + c) = __floats2bfloat162_rn(v2, v3);
            }
        __syncthreads();

        // GEMM2: H1[128x128] @ W2[128x64] (resident)
        float acc2[2][4][4];
#pragma unroll
        for (int a = 0; a < 2; ++a)
#pragma unroll
            for (int bq = 0; bq < 4; ++bq)
#pragma unroll
                for (int cq = 0; cq < 4; ++cq) acc2[a][bq][cq] = 0.f;

#pragma unroll
        for (int ch = 0; ch < 4; ++ch)
#pragma unroll
            for (int kk = 0; kk < 2; ++kk) {
                unsigned a0[4], a1[4];
                int ar = wm * 32 + (lane & 15), ac = ch * 32 + kk * 16 + (lane >> 4) * 8;
                ldm_x4(a0, cvta_s(H1s + ar * 136 + ac));
                ldm_x4(a1, cvta_s(H1s + (ar + 16) * 136 + ac));
                int br = ch * 32 + kk * 16 + (lane & 15);
#pragma unroll
                for (int p = 0; p < 2; ++p) {
                    unsigned bb[4];
                    ldm_x4t(bb, cvta_s(W2s + br * 72 + wn * 32 + p * 16 + (lane >> 4) * 8));
                    mma16816(acc2[0][2 * p],     a0, bb[0], bb[1]);
                    mma16816(acc2[1][2 * p],     a1, bb[0], bb[1]);
                    mma16816(acc2[0][2 * p + 1], a0, bb[2], bb[3]);
                    mma16816(acc2[1][2 * p + 1], a1, bb[2], bb[3]);
                }
            }

        // epilogue GEMM2 + GEMM3 dot in registers
        float sd[4] = {0.f, 0.f, 0.f, 0.f};
#pragma unroll
        for (int mi = 0; mi < 2; ++mi)
#pragma unroll
            for (int nj = 0; nj < 4; ++nj) {
                int c = wn * 32 + nj * 8 + (lane & 3) * 2;
                float w0 = w3s[c], w1 = w3s[c + 1];
                float ba = b2s[c], bbv = b2s[c + 1];
                sd[mi * 2 + 0] += fmaxf(acc2[mi][nj][0] + ba,  0.f) * w0
                                + fmaxf(acc2[mi][nj][1] + bbv, 0.f) * w1;
                sd[mi * 2 + 1] += fmaxf(acc2[mi][nj][2] + ba,  0.f) * w0
                                + fmaxf(acc2[mi][nj][3] + bbv, 0.f) * w1;
            }
#pragma unroll
        for (int q = 0; q < 4; ++q) {
            sd[q] += __shfl_xor_sync(0xffffffffu, sd[q], 1);
            sd[q] += __shfl_xor_sync(0xffffffffu, sd[q], 2);
        }
        if ((lane & 3) == 0) {
#pragma unroll
            for (int q = 0; q < 4; ++q) {
                int r = wm * 32 + (q >> 1) * 16 + (q & 1) * 8 + (lane >> 2);
                red[wn * 128 + r] = sd[q];
            }
        }
        __syncthreads();
        if (tid < 128) {
            float z = red[tid] + red[128 + tid] + __ldg(eb3 + e);
            out[(size_t)BN * 17 + (size_t)(m0 + tid) * EE + e] = 1.f / (1.f + expf(-z));
        }
    } else {
        // ================= ROUTER PATH =================
        __nv_bfloat16* Xb0 = (__nv_bfloat16*)sm;
        __nv_bfloat16* Xb1 = (__nv_bfloat16*)(sm + 10240);
        __nv_bfloat16* Wr0 = (__nv_bfloat16*)(sm + 20480);
        __nv_bfloat16* Wr1 = (__nv_bfloat16*)(sm + 25088);
        float* H1r  = (float*)sm;
        float* rW2s = (float*)(sm + 34816);
        float* rW3s = (float*)(sm + 43008);
        float* rb2s = (float*)(sm + 45056);
        float* rb3s = (float*)(sm + 45184);

        const int wm = w & 3;
        const int wn = w >> 2;

        for (int i = tid; i < RR1 * RR2; i += 256) rW2s[i] = rW2[i];
        for (int i = tid; i < RR2 * EE;  i += 256) rW3s[i] = rW3[i];
        if (tid < RR2) rb2s[tid] = rb2[tid];
        if (tid < EE)  rb3s[tid] = rb3[tid];

        const __nv_bfloat16* Xp = g_xb + (size_t)m0 * DD;
        const int x_r = tid >> 2, x_c = (tid & 3) * 8;
        const int r_r = tid >> 3, r_c = (tid & 7) * 8;

        __nv_bfloat16* XB[2] = {Xb0, Xb1};
        __nv_bfloat16* WB[2] = {Wr0, Wr1};

        auto issue = [&](int c, int b) {
            const __nv_bfloat16* xs = Xp + (size_t)x_r * DD + c * 32 + x_c;
            cp16(XB[b] + x_r * 40 + x_c, xs);
            cp16(XB[b] + (x_r + 64) * 40 + x_c, xs + (size_t)64 * DD);
            cp16(WB[b] + r_r * 72 + r_c, g_rW1b + (c * 32 + r_r) * RR1 + r_c);
        };

        float acc[2][4][4];
#pragma unroll
        for (int a = 0; a < 2; ++a)
#pragma unroll
            for (int bq = 0; bq < 4; ++bq)
#pragma unroll
                for (int cq = 0; cq < 4; ++cq) acc[a][bq][cq] = 0.f;

        issue(0, 0); cp_commit();
        issue(1, 1); cp_commit();
        for (int c = 0; c < DD / 32; ++c) {
            cp_wait<1>(); __syncthreads();
            int b = c & 1;
#pragma unroll
            for (int kk = 0; kk < 2; ++kk) {
                unsigned a0[4], a1[4];
                int ar = wm * 32 + (lane & 15), ac = kk * 16 + (lane >> 4) * 8;
                ldm_x4(a0, cvta_s(XB[b] + ar * 40 + ac));
                ldm_x4(a1, cvta_s(XB[b] + (ar + 16) * 40 + ac));
                int br = kk * 16 + (lane & 15);
#pragma unroll
                for (int p = 0; p < 2; ++p) {
                    unsigned bb[4];
                    ldm_x4t(bb, cvta_s(WB[b] + br * 72 + wn * 32 + p * 16 + (lane >> 4) * 8));
                    mma16816(acc[0][2 * p],     a0, bb[0], bb[1]);
                    mma16816(acc[1][2 * p],     a1, bb[0], bb[1]);
                    mma16816(acc[0][2 * p + 1], a0, bb[2], bb[3]);
                    mma16816(acc[1][2 * p + 1], a1, bb[2], bb[3]);
                }
            }
            __syncthreads();
            if (c + 2 < DD / 32) issue(c + 2, b);
            cp_commit();
        }

#pragma unroll
        for (int mi = 0; mi < 2; ++mi)
#pragma unroll
            for (int nj = 0; nj < 4; ++nj) {
                int r = wm * 32 + mi * 16 + (lane >> 2);
                int c = wn * 32 + nj * 8 + (lane & 3) * 2;
                float ba = g_rb1eff[c], bbv = g_rb1eff[c + 1];
                H1r[r * 67 + c]           = fmaxf(acc[mi][nj][0] + ba,  0.f);
                H1r[r * 67 + c + 1]       = fmaxf(acc[mi][nj][1] + bbv, 0.f);
                H1r[(r + 8) * 67 + c]     = fmaxf(acc[mi][nj][2] + ba,  0.f);
                H1r[(r + 8) * 67 + c + 1] = fmaxf(acc[mi][nj][3] + bbv, 0.f);
            }
        __syncthreads();

        if (tid < 128) {
            const float* h1 = H1r + tid * 67;
            float h2[RR2];
#pragma unroll 4
            for (int j = 0; j < RR2; ++j) {
                float s = rb2s[j];
                for (int i = 0; i < RR1; ++i) s += h1[i] * rW2s[i * RR2 + j];
                h2[j] = fmaxf(s, 0.f);
            }
            float lg[EE];
#pragma unroll
            for (int t = 0; t < EE; ++t) {
                float s = rb3s[t];
#pragma unroll
                for (int j = 0; j < RR2; ++j) s += h2[j] * rW3s[j * EE + t];
                lg[t] = s;
            }
            float mx = lg[0];
#pragma unroll
            for (int t = 1; t < EE; ++t) mx = fmaxf(mx, lg[t]);
            float ex[EE]; float den = 0.f;
#pragma unroll
            for (int t = 0; t < EE; ++t) { ex[t] = expf(lg[t] - mx); den += ex[t]; }
            float inv = 1.f / den;
            float* o = out + BN + (size_t)(m0 + tid) * EE;
#pragma unroll
            for (int t = 0; t < EE; ++t) o[t] = ex[t] * inv;
        }
    }
}

// ---------------- combine ----------------
__global__ void combine_kernel(float* __restrict__ out) {
    int i = blockIdx.x * 256 + threadIdx.x;
    const float4* rw = (const float4*)(out + BN + (size_t)i * EE);
    const float4* eo = (const float4*)(out + (size_t)BN * 17 + (size_t)i * EE);
    float s = 0.f;
#pragma unroll
    for (int q = 0; q < 4; ++q) {
        float4 a = rw[q], b = eo[q];
        s += a.x * b.x + a.y * b.y + a.z * b.z + a.w * b.w;
    }
    out[i] = s;
}

// ---------------- launcher ----------------
extern "C" void kernel_launch(void* const* d_in, const int* in_sizes, int n_in,
                              void* d_out, int out_size) {
    const float* x       = (const float*)d_in[0];
    const float* r_gamma = (const float*)d_in[1];
    const float* r_beta  = (const float*)d_in[2];
    const float* r_mean  = (const float*)d_in[3];
    const float* r_var   = (const float*)d_in[4];
    const float* rW1     = (const float*)d_in[5];
    const float* rb1     = (const float*)d_in[6];
    const float* rW2     = (const float*)d_in[7];
    const float* rb2     = (const float*)d_in[8];
    const float* rW3     = (const float*)d_in[9];
    const float* rb3     = (const float*)d_in[10];
    const float* e_gamma = (const float*)d_in[11];
    const float* e_beta  = (const float*)d_in[12];
    const float* e_mean  = (const float*)d_in[13];
    const float* e_var   = (const float*)d_in[14];
    const float* eW1     = (const float*)d_in[15];
    const float* eb1     = (const float*)d_in[16];
    const float* eW2     = (const float*)d_in[17];
    const float* eb2     = (const float*)d_in[18];
    const float* eW3     = (const float*)d_in[19];
    const float* eb3     = (const float*)d_in[20];
    float* out = (float*)d_out;

    cudaFuncSetAttribute(fused_kernel, cudaFuncAttributeMaxDynamicSharedMemorySize,
                         SMEM_TOT);

    k_conv_x<<<(BN * (size_t)DD) / (256 * 8), 256>>>(x);                              // 0
    k_prep_router<<<320, 256>>>(rW1, r_gamma, r_beta, r_mean, r_var, rb1);            // 1
    k_prep_expert<<<10752, 256>>>(eW1, e_gamma, e_var, eW2, e_beta, e_mean, eb1);     // 2
    fused_kernel<<<dim3(EE + 1, BN / TMX), 256, SMEM_TOT>>>(                          // 3 (profiled)
        eb2, eW3, eb3, rW2, rb2, rW3, rb3, out);
    combine_kernel<<<BN / 256, 256>>>(out);                                           // 4
}